// round 12
// baseline (speedup 1.0000x reference)
#include <cuda_runtime.h>
#include <cuda_bf16.h>
#include <cstdint>

#define BDIM 4
#define SQ 2048
#define SK 2048
#define DD 1024
#define EPSV 1e-8f
#define NEGV -1000000000.0f

#define BM 128
#define BN 256
#define KC 64              // bf16 elems per K stage
#define NKT (DD / KC)      // 16 k-tiles
#define PIPE 3
#define KBYTES (KC * 2)    // 128 bytes per row
#define TILEB_A (BM * KBYTES)          // 16 KB
#define TILEB_B (BN * KBYTES)          // 32 KB
#define STAGEB (TILEB_A + TILEB_B)     // 48 KB
#define SMEM_TOTAL (PIPE * STAGEB)     // 147456

// bf16 staging copies + inverse norms (device globals: no allocation allowed)
__device__ __nv_bfloat16 g_qb[(size_t)BDIM * SQ * DD];
__device__ __nv_bfloat16 g_kb[(size_t)BDIM * SK * DD];
__device__ float g_inv_qn[BDIM * SQ];
__device__ float g_inv_kn[BDIM * SK];

__device__ __forceinline__ uint32_t smem_u32(const void* p) {
    uint32_t a;
    asm("{ .reg .u64 t; cvta.to.shared.u64 t, %1; cvt.u32.u64 %0, t; }" : "=r"(a) : "l"(p));
    return a;
}

__device__ __forceinline__ uint32_t swz(uint32_t off) {
    // 16B-chunk XOR swizzle within 128B rows
    return off ^ ((off >> 3) & 0x70);
}

#define CPASYNC16(dst, src) \
    asm volatile("cp.async.cg.shared.global [%0], [%1], 16;" :: "r"(dst), "l"(src))
#define CPCOMMIT() asm volatile("cp.async.commit_group;" ::: "memory")
#define CPWAIT(n) asm volatile("cp.async.wait_group %0;" :: "n"(n) : "memory")

#define LDMATRIX_X4(r0, r1, r2, r3, addr) \
    asm volatile("ldmatrix.sync.aligned.m8n8.x4.shared.b16 {%0,%1,%2,%3}, [%4];" \
                 : "=r"(r0), "=r"(r1), "=r"(r2), "=r"(r3) : "r"(addr))

#define MMA16816(d, a, b0, b1) \
    asm volatile("mma.sync.aligned.m16n8k16.row.col.f32.bf16.bf16.f32 " \
                 "{%0,%1,%2,%3}, {%4,%5,%6,%7}, {%8,%9}, {%0,%1,%2,%3};" \
                 : "+f"((d)[0]), "+f"((d)[1]), "+f"((d)[2]), "+f"((d)[3]) \
                 : "r"((a)[0]), "r"((a)[1]), "r"((a)[2]), "r"((a)[3]), "r"(b0), "r"(b1))

// ---------------------------------------------------------------------------
// Kernel 1: fused per-row inverse L2 norm + fp32 -> bf16 conversion.
// ---------------------------------------------------------------------------
__global__ __launch_bounds__(256) void norms_convert_kernel(const float* __restrict__ q,
                                                            const float* __restrict__ k) {
    const int row = blockIdx.x;
    const bool isQ = (row < BDIM * SQ);
    const int r = isQ ? row : row - BDIM * SQ;
    const float* src = (isQ ? q : k) + (size_t)r * DD;
    __nv_bfloat16* dst = (isQ ? g_qb : g_kb) + (size_t)r * DD;
    float* o = isQ ? &g_inv_qn[r] : &g_inv_kn[r];

    float4 v = reinterpret_cast<const float4*>(src)[threadIdx.x];
    __nv_bfloat162 p0, p1;
    p0.x = __float2bfloat16(v.x); p0.y = __float2bfloat16(v.y);
    p1.x = __float2bfloat16(v.z); p1.y = __float2bfloat16(v.w);
    reinterpret_cast<__nv_bfloat162*>(dst)[threadIdx.x * 2 + 0] = p0;
    reinterpret_cast<__nv_bfloat162*>(dst)[threadIdx.x * 2 + 1] = p1;

    float s = v.x * v.x + v.y * v.y + v.z * v.z + v.w * v.w;
    #pragma unroll
    for (int off = 16; off > 0; off >>= 1) s += __shfl_xor_sync(0xffffffffu, s, off);
    __shared__ float red[8];
    if ((threadIdx.x & 31) == 0) red[threadIdx.x >> 5] = s;
    __syncthreads();
    if (threadIdx.x < 8) {
        float t = red[threadIdx.x];
        #pragma unroll
        for (int off = 4; off > 0; off >>= 1) t += __shfl_xor_sync(0xffu, t, off);
        if (threadIdx.x == 0) *o = 1.0f / fmaxf(sqrtf(t), EPSV);
    }
}

// ---------------------------------------------------------------------------
// Kernel 2: bf16 mma.sync GEMM (NT), 128x256 CTA tile, 3-stage cp.async pipe,
// fused cosine-scale + mask epilogue.
// Warp layout: 8 warps = 2 (M) x 4 (N); warp tile 64x64 = 4 m16 x 8 n8.
// ---------------------------------------------------------------------------
__global__ __launch_bounds__(256) void score_kernel(const int* __restrict__ mask,
                                                    float* __restrict__ out) {
    extern __shared__ __align__(1024) char smem[];
    const uint32_t sbase = smem_u32(smem);

    const int t = threadIdx.x;
    const int wid = t >> 5, lane = t & 31;
    const int b = blockIdx.z, tm = blockIdx.y, tn = blockIdx.x;
    const int warp_m = wid & 1;   // 0..1 -> 64-row halves
    const int warp_n = wid >> 1;  // 0..3 -> 64-col quarters of 256

    const __nv_bfloat16* Aq = g_qb + ((size_t)b * SQ + tm * BM) * DD;
    const __nv_bfloat16* Bk = g_kb + ((size_t)b * SK + tn * BN) * DD;

    const int ld_c = t & 7;     // 16B chunk in 128B row
    const int ld_r0 = t >> 3;   // 0..31

    // ldmatrix lane addressing
    const int a_row_base = warp_m * 64 + (lane & 15);
    const int a_c16 = lane >> 4;                                   // 0..1
    const int b_row_base = warp_n * 64 + ((lane >> 4) & 1) * 8 + (lane & 7);
    const int b_c16 = (lane >> 3) & 1;

    float acc[4][8][4];
    #pragma unroll
    for (int mi = 0; mi < 4; mi++)
        #pragma unroll
        for (int ni = 0; ni < 8; ni++)
            #pragma unroll
            for (int e = 0; e < 4; e++) acc[mi][ni][e] = 0.0f;

    // stage loader: 384 rows (128 A + 256 B) x 8 chunks = 3072 x 16B; 12/thread
    auto load_stage = [&](int s, int kt) {
        uint32_t ab = sbase + s * STAGEB;
        uint32_t bb = ab + TILEB_A;
        #pragma unroll
        for (int it = 0; it < 12; it++) {
            int row = it * 32 + ld_r0;    // 0..383
            if (row < BM) {
                const __nv_bfloat16* sa = Aq + (size_t)row * DD + kt * KC + ld_c * 8;
                CPASYNC16(ab + swz(row * KBYTES + ld_c * 16), sa);
            } else {
                int rb = row - BM;        // 0..255
                const __nv_bfloat16* sb = Bk + (size_t)rb * DD + kt * KC + ld_c * 8;
                CPASYNC16(bb + swz(rb * KBYTES + ld_c * 16), sb);
            }
        }
        CPCOMMIT();
    };

    load_stage(0, 0);
    load_stage(1, 1);

    for (int kt = 0; kt < NKT; kt++) {
        if (kt >= NKT - 2) { CPWAIT(0); } else { CPWAIT(1); }
        __syncthreads();
        if (kt + 2 < NKT) load_stage((kt + 2) % PIPE, kt + 2);

        const uint32_t ab = sbase + (kt % PIPE) * STAGEB;
        const uint32_t bb = ab + TILEB_A;

        #pragma unroll
        for (int ks = 0; ks < 4; ks++) {
            uint32_t af[4][4];
            #pragma unroll
            for (int mi = 0; mi < 4; mi++) {
                int row = a_row_base + mi * 16;
                LDMATRIX_X4(af[mi][0], af[mi][1], af[mi][2], af[mi][3],
                            ab + swz(row * KBYTES + (ks * 2 + a_c16) * 16));
            }
            uint32_t bfr[4][4];
            #pragma unroll
            for (int pj = 0; pj < 4; pj++) {
                int row = b_row_base + pj * 16;
                LDMATRIX_X4(bfr[pj][0], bfr[pj][1], bfr[pj][2], bfr[pj][3],
                            bb + swz(row * KBYTES + (ks * 2 + b_c16) * 16));
            }
            #pragma unroll
            for (int mi = 0; mi < 4; mi++)
                #pragma unroll
                for (int ni = 0; ni < 8; ni++)
                    MMA16816(acc[mi][ni], af[mi], bfr[ni >> 1][(ni & 1) * 2],
                             bfr[ni >> 1][(ni & 1) * 2 + 1]);
        }
        // next iteration's top barrier orders reads before buffer overwrite
    }

    // ---- epilogue: cosine scaling + mask, float2 stores ----
    const int tig = lane & 3;

    float iq[4][2];
    #pragma unroll
    for (int mi = 0; mi < 4; mi++) {
        int r0 = tm * BM + warp_m * 64 + mi * 16 + (lane >> 2);
        iq[mi][0] = g_inv_qn[b * SQ + r0];
        iq[mi][1] = g_inv_qn[b * SQ + r0 + 8];
    }

    #pragma unroll
    for (int ni = 0; ni < 8; ni++) {
        int c0 = tn * BN + warp_n * 64 + ni * 8 + 2 * tig;
        float ik0 = g_inv_kn[b * SK + c0];
        float ik1 = g_inv_kn[b * SK + c0 + 1];
        int mk0 = mask[b * SK + c0];
        int mk1 = mask[b * SK + c0 + 1];
        #pragma unroll
        for (int mi = 0; mi < 4; mi++) {
            int r0 = tm * BM + warp_m * 64 + mi * 16 + (lane >> 2);
            float2 v0, v1;
            v0.x = (mk0 == 0) ? NEGV : acc[mi][ni][0] * iq[mi][0] * ik0;
            v0.y = (mk1 == 0) ? NEGV : acc[mi][ni][1] * iq[mi][0] * ik1;
            v1.x = (mk0 == 0) ? NEGV : acc[mi][ni][2] * iq[mi][1] * ik0;
            v1.y = (mk1 == 0) ? NEGV : acc[mi][ni][3] * iq[mi][1] * ik1;
            *reinterpret_cast<float2*>(out + ((size_t)b * SQ + r0) * SK + c0) = v0;
            *reinterpret_cast<float2*>(out + ((size_t)b * SQ + r0 + 8) * SK + c0) = v1;
        }
    }
}

// ---------------------------------------------------------------------------
extern "C" void kernel_launch(void* const* d_in, const int* in_sizes, int n_in,
                              void* d_out, int out_size) {
    const float* q = (const float*)d_in[0];   // (4, 2048, 1, 1024) f32
    const float* k = (const float*)d_in[1];   // (4, 1, 2048, 1024) f32
    const int* mask = (const int*)d_in[2];    // (4, 2048) i32
    float* out = (float*)d_out;               // (4, 2048, 2048) f32

    cudaFuncSetAttribute(score_kernel, cudaFuncAttributeMaxDynamicSharedMemorySize, SMEM_TOTAL);

    norms_convert_kernel<<<BDIM * SQ + BDIM * SK, 256>>>(q, k);

    dim3 grid(SK / BN, SQ / BM, BDIM);
    score_kernel<<<grid, 256, SMEM_TOTAL>>>(mask, out);
}

// round 13
// speedup vs baseline: 1.2846x; 1.2846x over previous
#include <cuda_runtime.h>
#include <cuda_bf16.h>
#include <cstdint>

#define BDIM 4
#define SQ 2048
#define SK 2048
#define DD 1024
#define EPSV 1e-8f
#define NEGV -1000000000.0f

#define BM 128
#define BN 128
#define KC 64              // bf16 elems per K stage
#define NKT (DD / KC)      // 16 k-tiles
#define PIPE 3
#define KBYTES (KC * 2)    // 128 bytes per row
#define TILEB (128 * KBYTES)       // 16 KB per operand tile
#define STAGEB (2 * TILEB)         // A + B
#define SMEM_TOTAL (PIPE * STAGEB) // 98304

// bf16 staging copies + inverse norms (device globals: no allocation allowed)
__device__ __nv_bfloat16 g_qb[(size_t)BDIM * SQ * DD];
__device__ __nv_bfloat16 g_kb[(size_t)BDIM * SK * DD];
__device__ float g_inv_qn[BDIM * SQ];
__device__ float g_inv_kn[BDIM * SK];

__device__ __forceinline__ uint32_t smem_u32(const void* p) {
    uint32_t a;
    asm("{ .reg .u64 t; cvta.to.shared.u64 t, %1; cvt.u32.u64 %0, t; }" : "=r"(a) : "l"(p));
    return a;
}

__device__ __forceinline__ uint32_t swz(uint32_t off) {
    // 16B-chunk XOR swizzle within 128B rows
    return off ^ ((off >> 3) & 0x70);
}

#define CPASYNC16(dst, src) \
    asm volatile("cp.async.cg.shared.global [%0], [%1], 16;" :: "r"(dst), "l"(src))
#define CPCOMMIT() asm volatile("cp.async.commit_group;" ::: "memory")
#define CPWAIT(n) asm volatile("cp.async.wait_group %0;" :: "n"(n) : "memory")

#define LDMATRIX_X4(r0, r1, r2, r3, addr) \
    asm volatile("ldmatrix.sync.aligned.m8n8.x4.shared.b16 {%0,%1,%2,%3}, [%4];" \
                 : "=r"(r0), "=r"(r1), "=r"(r2), "=r"(r3) : "r"(addr))

#define MMA16816(d, a, b0, b1) \
    asm volatile("mma.sync.aligned.m16n8k16.row.col.f32.bf16.bf16.f32 " \
                 "{%0,%1,%2,%3}, {%4,%5,%6,%7}, {%8,%9}, {%0,%1,%2,%3};" \
                 : "+f"((d)[0]), "+f"((d)[1]), "+f"((d)[2]), "+f"((d)[3]) \
                 : "r"((a)[0]), "r"((a)[1]), "r"((a)[2]), "r"((a)[3]), "r"(b0), "r"(b1))

// ---------------------------------------------------------------------------
// Kernel 1: fused per-row inverse L2 norm + fp32 -> bf16 conversion.
// One WARP per row (no smem, no block barriers), 8 rows per 256-thread block.
// Each lane: 8x float4 strided reads (MLP=8), shfl-only reduction.
// ---------------------------------------------------------------------------
__global__ __launch_bounds__(256) void norms_convert_kernel(const float* __restrict__ q,
                                                            const float* __restrict__ k) {
    const int row = blockIdx.x * 8 + (threadIdx.x >> 5);
    const int lane = threadIdx.x & 31;
    const bool isQ = (row < BDIM * SQ);
    const int r = isQ ? row : row - BDIM * SQ;
    const float* src = (isQ ? q : k) + (size_t)r * DD;
    __nv_bfloat16* dst = (isQ ? g_qb : g_kb) + (size_t)r * DD;
    float* o = isQ ? &g_inv_qn[r] : &g_inv_kn[r];

    const float4* src4 = reinterpret_cast<const float4*>(src);
    __nv_bfloat162* dst2 = reinterpret_cast<__nv_bfloat162*>(dst);

    // batch all 8 loads first (MLP=8), then convert/store + accumulate
    float4 v[8];
    #pragma unroll
    for (int i = 0; i < 8; i++) v[i] = src4[lane + 32 * i];

    float s = 0.0f;
    #pragma unroll
    for (int i = 0; i < 8; i++) {
        __nv_bfloat162 p0, p1;
        p0.x = __float2bfloat16(v[i].x); p0.y = __float2bfloat16(v[i].y);
        p1.x = __float2bfloat16(v[i].z); p1.y = __float2bfloat16(v[i].w);
        dst2[2 * (lane + 32 * i) + 0] = p0;
        dst2[2 * (lane + 32 * i) + 1] = p1;
        s += v[i].x * v[i].x + v[i].y * v[i].y + v[i].z * v[i].z + v[i].w * v[i].w;
    }

    #pragma unroll
    for (int off = 16; off > 0; off >>= 1) s += __shfl_xor_sync(0xffffffffu, s, off);
    if (lane == 0) *o = 1.0f / fmaxf(sqrtf(s), EPSV);
}

// ---------------------------------------------------------------------------
// Kernel 2: bf16 mma.sync GEMM (NT), 128x128 CTA tile, 3-stage cp.async pipe,
// software-pipelined fragment loads, fused cosine-scale + mask epilogue.
// Warp layout: 8 warps = 2 (M) x 4 (N); warp tile 64x32 = 4 m16 x 4 n8.
// (reverted to the measured 86.7us configuration; 2 CTAs/SM)
// ---------------------------------------------------------------------------
__global__ __launch_bounds__(256) void score_kernel(const int* __restrict__ mask,
                                                    float* __restrict__ out) {
    extern __shared__ __align__(1024) char smem[];
    const uint32_t sbase = smem_u32(smem);

    const int t = threadIdx.x;
    const int wid = t >> 5, lane = t & 31;
    const int b = blockIdx.z, tm = blockIdx.y, tn = blockIdx.x;
    const int warp_m = wid & 1;   // 0..1 -> 64-row halves
    const int warp_n = wid >> 1;  // 0..3 -> 32-col quarters

    const __nv_bfloat16* Aq = g_qb + ((size_t)b * SQ + tm * BM) * DD;
    const __nv_bfloat16* Bk = g_kb + ((size_t)b * SK + tn * BN) * DD;

    const int ld_c = t & 7;
    const int ld_r0 = t >> 3;

    const int a_row_base = warp_m * 64 + (lane & 15);
    const int a_c16 = lane >> 4;                                   // 0..1
    const int b_row_base = warp_n * 32 + ((lane >> 4) & 1) * 8 + (lane & 7);
    const int b_c16 = (lane >> 3) & 1;

    float acc[4][4][4];
    #pragma unroll
    for (int mi = 0; mi < 4; mi++)
        #pragma unroll
        for (int ni = 0; ni < 4; ni++)
            #pragma unroll
            for (int e = 0; e < 4; e++) acc[mi][ni][e] = 0.0f;

    auto load_stage = [&](int s, int kt) {
        uint32_t ab = sbase + s * STAGEB;
        uint32_t bb = ab + TILEB;
        #pragma unroll
        for (int it = 0; it < 4; it++) {
            int row = it * 32 + ld_r0;
            uint32_t doff = swz(row * KBYTES + ld_c * 16);
            const __nv_bfloat16* sa = Aq + (size_t)row * DD + kt * KC + ld_c * 8;
            const __nv_bfloat16* sb = Bk + (size_t)row * DD + kt * KC + ld_c * 8;
            CPASYNC16(ab + doff, sa);
            CPASYNC16(bb + doff, sb);
        }
        CPCOMMIT();
    };

    // double-buffered fragments
    uint32_t af[2][4][4];
    uint32_t bfr[2][2][4];

    auto load_frags = [&](uint32_t ab, uint32_t bb, int ks, int buf) {
        #pragma unroll
        for (int mi = 0; mi < 4; mi++) {
            int row = a_row_base + mi * 16;
            LDMATRIX_X4(af[buf][mi][0], af[buf][mi][1], af[buf][mi][2], af[buf][mi][3],
                        ab + swz(row * KBYTES + (ks * 2 + a_c16) * 16));
        }
        #pragma unroll
        for (int pj = 0; pj < 2; pj++) {
            int row = b_row_base + pj * 16;
            LDMATRIX_X4(bfr[buf][pj][0], bfr[buf][pj][1], bfr[buf][pj][2], bfr[buf][pj][3],
                        bb + swz(row * KBYTES + (ks * 2 + b_c16) * 16));
        }
    };

    load_stage(0, 0);
    load_stage(1, 1);

    for (int kt = 0; kt < NKT; kt++) {
        if (kt >= NKT - 2) { CPWAIT(0); } else { CPWAIT(1); }
        __syncthreads();
        if (kt + 2 < NKT) load_stage((kt + 2) % PIPE, kt + 2);

        const uint32_t ab = sbase + (kt % PIPE) * STAGEB;
        const uint32_t bb = ab + TILEB;

        load_frags(ab, bb, 0, 0);

        #pragma unroll
        for (int ks = 0; ks < 4; ks++) {
            const int cur = ks & 1;
            if (ks < 3) load_frags(ab, bb, ks + 1, cur ^ 1);
            #pragma unroll
            for (int mi = 0; mi < 4; mi++)
                #pragma unroll
                for (int ni = 0; ni < 4; ni++)
                    MMA16816(acc[mi][ni], af[cur][mi], bfr[cur][ni >> 1][(ni & 1) * 2],
                             bfr[cur][ni >> 1][(ni & 1) * 2 + 1]);
        }
    }

    // ---- epilogue: cosine scaling + mask, float2 stores ----
    const int tig = lane & 3;

    float iq[4][2];
    #pragma unroll
    for (int mi = 0; mi < 4; mi++) {
        int r0 = tm * BM + warp_m * 64 + mi * 16 + (lane >> 2);
        iq[mi][0] = g_inv_qn[b * SQ + r0];
        iq[mi][1] = g_inv_qn[b * SQ + r0 + 8];
    }
    float ik[4][2];
    int mk[4][2];
    #pragma unroll
    for (int ni = 0; ni < 4; ni++) {
        int c0 = tn * BN + warp_n * 32 + ni * 8 + 2 * tig;
        ik[ni][0] = g_inv_kn[b * SK + c0];
        ik[ni][1] = g_inv_kn[b * SK + c0 + 1];
        mk[ni][0] = mask[b * SK + c0];
        mk[ni][1] = mask[b * SK + c0 + 1];
    }

    #pragma unroll
    for (int mi = 0; mi < 4; mi++) {
        int r0 = tm * BM + warp_m * 64 + mi * 16 + (lane >> 2);
        #pragma unroll
        for (int ni = 0; ni < 4; ni++) {
            int c0 = tn * BN + warp_n * 32 + ni * 8 + 2 * tig;
            float2 v0, v1;
            v0.x = (mk[ni][0] == 0) ? NEGV : acc[mi][ni][0] * iq[mi][0] * ik[ni][0];
            v0.y = (mk[ni][1] == 0) ? NEGV : acc[mi][ni][1] * iq[mi][0] * ik[ni][1];
            v1.x = (mk[ni][0] == 0) ? NEGV : acc[mi][ni][2] * iq[mi][1] * ik[ni][0];
            v1.y = (mk[ni][1] == 0) ? NEGV : acc[mi][ni][3] * iq[mi][1] * ik[ni][1];
            *reinterpret_cast<float2*>(out + ((size_t)b * SQ + r0) * SK + c0) = v0;
            *reinterpret_cast<float2*>(out + ((size_t)b * SQ + r0 + 8) * SK + c0) = v1;
        }
    }
}

// ---------------------------------------------------------------------------
extern "C" void kernel_launch(void* const* d_in, const int* in_sizes, int n_in,
                              void* d_out, int out_size) {
    const float* q = (const float*)d_in[0];   // (4, 2048, 1, 1024) f32
    const float* k = (const float*)d_in[1];   // (4, 1, 2048, 1024) f32
    const int* mask = (const int*)d_in[2];    // (4, 2048) i32
    float* out = (float*)d_out;               // (4, 2048, 2048) f32

    cudaFuncSetAttribute(score_kernel, cudaFuncAttributeMaxDynamicSharedMemorySize, SMEM_TOTAL);

    // 16384 rows total, 8 rows (warps) per block
    norms_convert_kernel<<<(BDIM * SQ + BDIM * SK) / 8, 256>>>(q, k);

    dim3 grid(SK / BN, SQ / BM, BDIM);
    score_kernel<<<grid, 256, SMEM_TOTAL>>>(mask, out);
}